// round 5
// baseline (speedup 1.0000x reference)
#include <cuda_runtime.h>

// out[r] = W[0] + b + sum_i x_i * ( W[1+i] + sum_{j>=i} Wq[i,j]*x_j )
//
// 4 warps per 32-row group, warp p handles triangle rows i == p (mod 4).
// Template specialization keeps every index compile-time (registers, not
// local mem); branch is warp-uniform; weight LDS is full-warp broadcast.
// Block: 256 thr = 2 groups x 4 parity warps; 64 rows/block; grid = 512.

#define DIMS  64
#define DPAD  68
#define TPB   256
#define RPB   64            // rows per block
#define NBLK  512

#define SMEM_FLOATS (RPB*DPAD + DIMS*DPAD + DIMS + 8*32)

template<int P>
__device__ __forceinline__ float quarter_sum(const float* __restrict__ w2,
                                             const float* __restrict__ wlin,
                                             const float xr[DPAD])
{
    float acc = 0.0f;
    #pragma unroll
    for (int m = 0; m < DIMS / 4; m++) {
        const int i  = 4 * m + P;                    // compile-time
        const int Lp = (DIMS - i + 3) & ~3;          // padded row length
        float s0 = wlin[i];                           // fold linear term
        float s1 = 0.0f;
        #pragma unroll
        for (int t4 = 0; t4 < Lp / 4; t4++) {
            const float4 w = *reinterpret_cast<const float4*>(&w2[i * DPAD + 4 * t4]);
            s0 = fmaf(w.x, xr[i + 4*t4 + 0], s0);
            s1 = fmaf(w.y, xr[i + 4*t4 + 1], s1);
            s0 = fmaf(w.z, xr[i + 4*t4 + 2], s0);
            s1 = fmaf(w.w, xr[i + 4*t4 + 3], s1);
        }
        acc = fmaf(xr[i], s0 + s1, acc);
    }
    return acc;
}

__global__ void __launch_bounds__(TPB, 2)
poly_model_kernel(const float* __restrict__ x,
                  const float* __restrict__ W,
                  const float* __restrict__ bias,
                  float* __restrict__ out)
{
    extern __shared__ float smem[];
    float* xs   = smem;                       // RPB * DPAD
    float* w2   = xs + RPB * DPAD;            // DIMS * DPAD (zero-padded rows)
    float* wlin = w2 + DIMS * DPAD;           // DIMS
    float* red  = wlin + DIMS;                // 8 warps * 32 lanes

    const int tid = threadIdx.x;

    // Padded triangular weight matrix.
    for (int idx = tid; idx < DIMS * DPAD; idx += TPB) {
        const int i = idx / DPAD;
        const int t = idx - i * DPAD;
        float v = 0.0f;
        if (i + t < DIMS) {
            const int base = 1 + DIMS + i * DIMS - (i * (i - 1)) / 2;
            v = W[base + t];
        }
        w2[idx] = v;
    }
    if (tid < DIMS) wlin[tid] = W[1 + tid];

    // Coalesced x tile: 64 rows x 16 float4 = 1024 float4.
    const float4* xg = reinterpret_cast<const float4*>(x)
                     + (size_t)blockIdx.x * RPB * (DIMS / 4);
    #pragma unroll
    for (int k = 0; k < RPB * (DIMS / 4) / TPB; k++) {    // 4 iters
        const int q  = tid + k * TPB;
        const int r  = q >> 4;
        const int c4 = q & 15;
        *reinterpret_cast<float4*>(&xs[r * DPAD + c4 * 4]) = xg[q];
    }
    if (tid < RPB) {   // zero pad columns
        const float4 z = make_float4(0.f, 0.f, 0.f, 0.f);
        *reinterpret_cast<float4*>(&xs[tid * DPAD + DIMS]) = z;
    }
    __syncthreads();

    const int warp = tid >> 5;
    const int lane = tid & 31;
    const int p    = warp & 3;         // triangle-row parity (uniform per warp)
    const int g    = warp >> 2;        // row group 0/1
    const int rloc = g * 32 + lane;

    // Row into registers (17 LDS.128; one-time, minor conflicts ok).
    float xr[DPAD];
    #pragma unroll
    for (int k = 0; k < DPAD / 4; k++) {
        float4 v = *reinterpret_cast<const float4*>(&xs[rloc * DPAD + 4 * k]);
        xr[4*k + 0] = v.x;
        xr[4*k + 1] = v.y;
        xr[4*k + 2] = v.z;
        xr[4*k + 3] = v.w;
    }

    float acc;
    switch (p) {                                   // warp-uniform
        case 0:  acc = quarter_sum<0>(w2, wlin, xr); break;
        case 1:  acc = quarter_sum<1>(w2, wlin, xr); break;
        case 2:  acc = quarter_sum<2>(w2, wlin, xr); break;
        default: acc = quarter_sum<3>(w2, wlin, xr); break;
    }

    red[warp * 32 + lane] = acc;
    __syncthreads();

    if (p == 0) {
        const int b0 = warp * 32 + lane;
        float r_ = red[b0 + 32] + red[b0 + 64] + red[b0 + 96];
        out[blockIdx.x * RPB + rloc] = acc + r_ + W[0] + bias[0];
    }
}

extern "C" void kernel_launch(void* const* d_in, const int* in_sizes, int n_in,
                              void* d_out, int out_size)
{
    const float* x    = (const float*)d_in[0];  // [32768, 64]
    const float* W    = (const float*)d_in[1];  // [2145]
    const float* bias = (const float*)d_in[2];  // [1]
    float* out = (float*)d_out;                 // [32768]

    cudaFuncSetAttribute(poly_model_kernel,
                         cudaFuncAttributeMaxDynamicSharedMemorySize,
                         SMEM_FLOATS * 4);
    poly_model_kernel<<<NBLK, TPB, SMEM_FLOATS * 4>>>(x, W, bias, out);
}

// round 7
// speedup vs baseline: 1.2966x; 1.2966x over previous
#include <cuda_runtime.h>

// out[r] = W0 + b + sum_j x_j * y_j,  where y_j = Wlin[j] + sum_{i<=j} Wq[i,j]*x_i
// Rank-1-update formulation: 64 independent accumulators y_j, so every FFMA
// in a triangle row hits a distinct register -> ~64-way ILP (vs chain ILP 2).
//
// Weights staged in shared as zero-padded 64x68 rows (aligned LDS.128,
// full-warp broadcast, compile-time offsets). Grid=148 (one CTA/SM,
// balanced strided row map, avoids low-grid I$ throttle for ~46KB body).

#define DIMS  64
#define DPAD  68
#define NROWS 32768
#define TPB   256
#define GRID  148

__global__ void __launch_bounds__(TPB, 1)
poly_model_kernel(const float* __restrict__ x,
                  const float* __restrict__ W,
                  const float* __restrict__ bias,
                  float* __restrict__ out)
{
    __shared__ float w2[DIMS * DPAD];   // zero-padded triangular rows
    __shared__ float wlin[DPAD];        // linear weights, zero-padded

    const int tid = threadIdx.x;

    for (int idx = tid; idx < DIMS * DPAD; idx += TPB) {
        const int i = idx / DPAD;
        const int t = idx - i * DPAD;
        float v = 0.0f;
        if (t < DIMS - i) {
            const int base = 1 + DIMS + i * DIMS - (i * (i - 1)) / 2;
            v = W[base + t];
        }
        w2[idx] = v;
    }
    if (tid < DPAD) wlin[tid] = (tid < DIMS) ? W[1 + tid] : 0.0f;
    __syncthreads();

    // Balanced strided row mapping (each SM handles ~221 rows).
    const int row = tid * GRID + (int)blockIdx.x;
    if (row >= NROWS) return;

    // Row into registers (16 x LDG.128), zero-pad to 68.
    float xr[DPAD];
    const float4* xp = reinterpret_cast<const float4*>(x + (size_t)row * DIMS);
    #pragma unroll
    for (int q = 0; q < DIMS / 4; q++) {
        float4 v = xp[q];
        xr[4*q + 0] = v.x;
        xr[4*q + 1] = v.y;
        xr[4*q + 2] = v.z;
        xr[4*q + 3] = v.w;
    }
    xr[64] = xr[65] = xr[66] = xr[67] = 0.0f;

    // Independent accumulators, init with linear weights.
    float y[DPAD];
    #pragma unroll
    for (int k = 0; k < DPAD / 4; k++) {
        float4 v = *reinterpret_cast<const float4*>(&wlin[4 * k]);
        y[4*k + 0] = v.x;
        y[4*k + 1] = v.y;
        y[4*k + 2] = v.z;
        y[4*k + 3] = v.w;
    }

    // Triangle sweep: row i updates y[i..] with scalar multiplier x_i.
    #pragma unroll
    for (int i = 0; i < DIMS; i++) {
        const float xi = xr[i];
        const int Lp = (DIMS - i + 3) & ~3;          // padded row length
        #pragma unroll
        for (int t4 = 0; t4 < Lp / 4; t4++) {
            const float4 w = *reinterpret_cast<const float4*>(&w2[i * DPAD + 4 * t4]);
            y[i + 4*t4 + 0] = fmaf(w.x, xi, y[i + 4*t4 + 0]);
            y[i + 4*t4 + 1] = fmaf(w.y, xi, y[i + 4*t4 + 1]);
            y[i + 4*t4 + 2] = fmaf(w.z, xi, y[i + 4*t4 + 2]);
            y[i + 4*t4 + 3] = fmaf(w.w, xi, y[i + 4*t4 + 3]);
        }
    }

    // Final dot, 4 independent partials.
    float a0 = 0.f, a1 = 0.f, a2 = 0.f, a3 = 0.f;
    #pragma unroll
    for (int j = 0; j < DIMS; j += 4) {
        a0 = fmaf(xr[j + 0], y[j + 0], a0);
        a1 = fmaf(xr[j + 1], y[j + 1], a1);
        a2 = fmaf(xr[j + 2], y[j + 2], a2);
        a3 = fmaf(xr[j + 3], y[j + 3], a3);
    }

    out[row] = (a0 + a1) + (a2 + a3) + W[0] + bias[0];
}

extern "C" void kernel_launch(void* const* d_in, const int* in_sizes, int n_in,
                              void* d_out, int out_size)
{
    const float* x    = (const float*)d_in[0];  // [32768, 64]
    const float* W    = (const float*)d_in[1];  // [2145]
    const float* bias = (const float*)d_in[2];  // [1]
    float* out = (float*)d_out;                 // [32768]

    poly_model_kernel<<<GRID, TPB>>>(x, W, bias, out);
}